// round 6
// baseline (speedup 1.0000x reference)
#include <cuda_runtime.h>
#include <cuda_fp16.h>
#include <cuda_pipeline.h>
#include <mma.h>
#include <cstdint>

using namespace nvcuda;

#define N_NODES 16384
#define N_EDGES 131072
#define ED      32
#define NGRAPH  128
#define MAXF    1024
#define NEG_SLOPE 0.2f

// ---------------- scratch (static device memory; no allocs) ----------------
__device__ float g_hA[(size_t)N_NODES * MAXF];
__device__ float g_hB[(size_t)N_NODES * MAXF];
__device__ float g_xl[(size_t)N_NODES * MAXF];
__device__ float g_xr[(size_t)N_NODES * MAXF];
__device__ __half g_Ah[(size_t)N_NODES * MAXF];   // pre-split activations hi
__device__ __half g_Al[(size_t)N_NODES * MAXF];   // lo
__device__ __half g_B0h[524288], g_B0l[524288];   // Wl split
__device__ __half g_B1h[524288], g_B1l[524288];   // Wr split
__device__ float g_loop_attr[N_NODES * ED];
__device__ int   g_deg[N_NODES];
__device__ int   g_off[N_NODES + 1];
__device__ int   g_cur[N_NODES];
__device__ int   g_ssrc[N_EDGES];
__device__ int   g_sdst[N_EDGES];
__device__ int   g_seid[N_EDGES];
__device__ float g_elog[N_EDGES];
__device__ float g_eself[N_NODES];
__device__ float g_pool[NGRAPH * 256];
__device__ float g_z[NGRAPH * 64];

// ---------------- utility kernels ----------------
__global__ void zero_i(int* p, int n) {
    int i = blockIdx.x * blockDim.x + threadIdx.x;
    if (i < n) p[i] = 0;
}

__global__ void count_deg(const int* __restrict__ dst) {
    int i = blockIdx.x * blockDim.x + threadIdx.x;
    if (i < N_EDGES) atomicAdd(&g_deg[dst[i]], 1);
}

// exclusive scan of g_deg[16384] -> g_off (warp-shuffle, 1024 threads)
__global__ void scan_deg() {
    int tid = threadIdx.x, lane = tid & 31, warp = tid >> 5;
    int base = tid * 16;
    int loc[16];
    int s = 0;
#pragma unroll
    for (int k = 0; k < 16; k++) { loc[k] = s; s += g_deg[base + k]; }
    int mysum = s;
#pragma unroll
    for (int o = 1; o < 32; o <<= 1) {
        int v = __shfl_up_sync(0xffffffffu, s, o);
        if (lane >= o) s += v;
    }
    __shared__ int wsum[32];
    if (lane == 31) wsum[warp] = s;
    __syncthreads();
    if (warp == 0) {
        int v = wsum[lane];
#pragma unroll
        for (int o = 1; o < 32; o <<= 1) {
            int u = __shfl_up_sync(0xffffffffu, v, o);
            if (lane >= o) v += u;
        }
        wsum[lane] = v;
    }
    __syncthreads();
    int excl = s - mysum + (warp ? wsum[warp - 1] : 0);
#pragma unroll
    for (int k = 0; k < 16; k++) g_off[base + k] = excl + loc[k];
    if (tid == 1023) g_off[N_NODES] = excl + mysum;
}

__global__ void scatter_edges(const int* __restrict__ src, const int* __restrict__ dst) {
    int i = blockIdx.x * blockDim.x + threadIdx.x;
    if (i >= N_EDGES) return;
    int d = dst[i];
    int p = g_off[d] + atomicAdd(&g_cur[d], 1);
    g_ssrc[p] = src[i];
    g_sdst[p] = d;
    g_seid[p] = i;
}

// loop_attr[n] = mean of edge_attr over incoming edges (CSR, no atomics)
__global__ void loop_attr_csr(const float* __restrict__ ea) {
    int w = (blockIdx.x * blockDim.x + threadIdx.x) >> 5;
    int lane = threadIdx.x & 31;
    if (w >= N_NODES) return;
    int off = g_off[w], deg = g_off[w + 1] - off;
    float a = 0.0f;
    for (int j = 0; j < deg; j++)
        a += ea[(size_t)g_seid[off + j] * ED + lane];
    g_loop_attr[w * ED + lane] = a / fmaxf((float)deg, 1.0f);
}

// ---------------- fp32 -> (hi,lo) fp16 split ----------------
__global__ void split_kernel(const float* __restrict__ in,
                             __half* __restrict__ hi, __half* __restrict__ lo, int n) {
    int base = (blockIdx.x * blockDim.x + threadIdx.x) * 4;
    if (base >= n) return;
    float4 v = *reinterpret_cast<const float4*>(in + base);
    float vv[4] = {v.x, v.y, v.z, v.w};
    __half h[4], l[4];
#pragma unroll
    for (int i = 0; i < 4; i++) {
        h[i] = __float2half_rn(vv[i]);
        l[i] = __float2half_rn(vv[i] - __half2float(h[i]));
    }
    *reinterpret_cast<uint2*>(hi + base) = *reinterpret_cast<uint2*>(h);
    *reinterpret_cast<uint2*>(lo + base) = *reinterpret_cast<uint2*>(l);
}

// ------- pre-split fp16x2 GEMM, cp.async double-buffered, merged xl/xr -------
// C[M,N] = A@B (+bias), 3-product split accumulation. BM=BN=128, BK=32.
// grid.x = 2*Nw/128: first half -> (B0, bias0, C0), second half -> (B1, bias1, C1).
#define GS_LDA 40
#define GS_LDB 136
#define GS_AOFF_L 5120
#define GS_BOFF   10240
#define GS_BOFF_L 14592
#define GS_STAGE  18944
#define GS_SMEM   (2 * GS_STAGE * 2)

__global__ __launch_bounds__(256) void gemm_split(
    const __half* __restrict__ Ah, const __half* __restrict__ Al,
    const __half* __restrict__ B0h, const __half* __restrict__ B0l,
    const __half* __restrict__ B1h, const __half* __restrict__ B1l,
    const float* __restrict__ bias0, const float* __restrict__ bias1,
    float* __restrict__ C0, float* __restrict__ C1,
    int M, int Nw, int K) {
    extern __shared__ char gsm[];
    __half* sm = reinterpret_cast<__half*>(gsm);

    int tid = threadIdx.x;
    int warp = tid >> 5, lane = tid & 31;
    int wr = warp >> 2, wc = warp & 3;
    int nbx = Nw >> 7;
    int bx = blockIdx.x;
    const __half *Bh, *Bl;
    const float* bias;
    float* C;
    int col0;
    if (bx < nbx) { Bh = B0h; Bl = B0l; bias = bias0; C = C0; col0 = bx << 7; }
    else          { Bh = B1h; Bl = B1l; bias = bias1; C = C1; col0 = (bx - nbx) << 7; }
    int row0 = blockIdx.y << 7;

    wmma::fragment<wmma::accumulator, 16, 16, 16, float> cf[4][2];
#pragma unroll
    for (int r = 0; r < 4; r++)
#pragma unroll
        for (int c = 0; c < 2; c++) wmma::fill_fragment(cf[r][c], 0.0f);

    auto copy_stage = [&](int t) {
        int k0 = t * 32;
        __half* sb = sm + (t & 1) * GS_STAGE;
#pragma unroll
        for (int q = 0; q < 2; q++) {
            int idx = tid + q * 256;
            int r = idx >> 2, c = idx & 3;
            __pipeline_memcpy_async(&sb[r * GS_LDA + c * 8],
                                    &Ah[(size_t)(row0 + r) * K + k0 + c * 8], 16);
            __pipeline_memcpy_async(&sb[GS_AOFF_L + r * GS_LDA + c * 8],
                                    &Al[(size_t)(row0 + r) * K + k0 + c * 8], 16);
            int rb = idx >> 4, cb = idx & 15;
            __pipeline_memcpy_async(&sb[GS_BOFF + rb * GS_LDB + cb * 8],
                                    &Bh[(size_t)(k0 + rb) * Nw + col0 + cb * 8], 16);
            __pipeline_memcpy_async(&sb[GS_BOFF_L + rb * GS_LDB + cb * 8],
                                    &Bl[(size_t)(k0 + rb) * Nw + col0 + cb * 8], 16);
        }
    };
    auto compute = [&](int buf) {
        const __half* sb = sm + buf * GS_STAGE;
#pragma unroll
        for (int ks = 0; ks < 2; ks++) {
            wmma::fragment<wmma::matrix_a, 16, 16, 16, __half, wmma::row_major> ah[4], al[4];
            wmma::fragment<wmma::matrix_b, 16, 16, 16, __half, wmma::row_major> bh[2], bl[2];
#pragma unroll
            for (int r = 0; r < 4; r++) {
                int aoff = (wr * 64 + r * 16) * GS_LDA + ks * 16;
                wmma::load_matrix_sync(ah[r], &sb[aoff], GS_LDA);
                wmma::load_matrix_sync(al[r], &sb[GS_AOFF_L + aoff], GS_LDA);
            }
#pragma unroll
            for (int c = 0; c < 2; c++) {
                int boff = (ks * 16) * GS_LDB + wc * 32 + c * 16;
                wmma::load_matrix_sync(bh[c], &sb[GS_BOFF + boff], GS_LDB);
                wmma::load_matrix_sync(bl[c], &sb[GS_BOFF_L + boff], GS_LDB);
            }
#pragma unroll
            for (int r = 0; r < 4; r++)
#pragma unroll
                for (int c = 0; c < 2; c++) {
                    wmma::mma_sync(cf[r][c], ah[r], bl[c], cf[r][c]);
                    wmma::mma_sync(cf[r][c], al[r], bh[c], cf[r][c]);
                    wmma::mma_sync(cf[r][c], ah[r], bh[c], cf[r][c]);
                }
        }
    };

    int nk = K >> 5;
    copy_stage(0);
    __pipeline_commit();
    if (nk > 1) { copy_stage(1); __pipeline_commit(); }
    for (int t = 0; t < nk; t++) {
        if (t < nk - 1) __pipeline_wait_prior(1);
        else            __pipeline_wait_prior(0);
        __syncthreads();
        compute(t & 1);
        __syncthreads();
        if (t + 2 < nk) { copy_stage(t + 2); __pipeline_commit(); }
    }

    // epilogue: per-warp staging in (now free) smem
    float* Ep = reinterpret_cast<float*>(gsm) + warp * 16 * 20;
    int erow = lane >> 1;
    int ecol = (lane & 1) * 8;
#pragma unroll
    for (int r = 0; r < 4; r++) {
#pragma unroll
        for (int c = 0; c < 2; c++) {
            wmma::store_matrix_sync(Ep, cf[r][c], 20, wmma::mem_row_major);
            __syncwarp();
            int rr = row0 + wr * 64 + r * 16 + erow;
            int cc = col0 + wc * 32 + c * 16 + ecol;
            float4 v0 = *reinterpret_cast<float4*>(&Ep[erow * 20 + ecol]);
            float4 v1 = *reinterpret_cast<float4*>(&Ep[erow * 20 + ecol + 4]);
            float4 b0 = *reinterpret_cast<const float4*>(&bias[cc]);
            float4 b1 = *reinterpret_cast<const float4*>(&bias[cc + 4]);
            v0.x += b0.x; v0.y += b0.y; v0.z += b0.z; v0.w += b0.w;
            v1.x += b1.x; v1.y += b1.y; v1.z += b1.z; v1.w += b1.w;
            *reinterpret_cast<float4*>(&C[(size_t)rr * Nw + cc])     = v0;
            *reinterpret_cast<float4*>(&C[(size_t)rr * Nw + cc + 4]) = v1;
            __syncwarp();
        }
    }
}

// ------- fused attention logits: on-the-fly ea@We (fp16x2 wmma) + leakyrelu dot -------
#define FL_LDE 40
#define FL_LDW 136
#define FL_LDZ 132
#define FL_SMEM (2*128*FL_LDE*2 + 2*32*FL_LDW*2 + 128*FL_LDZ*4 + 2*128*4)

__global__ __launch_bounds__(256) void fused_logit(
    const float* __restrict__ ea_src, const float* __restrict__ We,
    const float* __restrict__ att,
    const float* __restrict__ xl, const float* __restrict__ xr,
    float* __restrict__ out_log, int F, int mode) {
    extern __shared__ char sm_raw[];
    __half* ea_h = reinterpret_cast<__half*>(sm_raw);
    __half* ea_l = ea_h + 128 * FL_LDE;
    __half* w_h  = ea_l + 128 * FL_LDE;
    __half* w_l  = w_h + 32 * FL_LDW;
    float*  sz   = reinterpret_cast<float*>(w_l + 32 * FL_LDW);
    int* s_src = reinterpret_cast<int*>(sz + 128 * FL_LDZ);
    int* s_dst = s_src + 128;

    int tid = threadIdx.x, warp = tid >> 5, lane = tid & 31;
    int wr = warp >> 2, wc = warp & 3;
    int tile0 = blockIdx.x * 128;

    if (tid < 128) {
        if (mode == 0) { s_src[tid] = g_ssrc[tile0 + tid]; s_dst[tid] = g_sdst[tile0 + tid]; }
        else           { s_src[tid] = tile0 + tid;         s_dst[tid] = tile0 + tid; }
    }
#pragma unroll
    for (int q = 0; q < 4; q++) {
        int lin = tid + q * 256;
        int r = lin >> 3, c4 = lin & 7;
        int row = (mode == 0) ? g_seid[tile0 + r] : (tile0 + r);
        float4 v = *reinterpret_cast<const float4*>(&ea_src[(size_t)row * ED + c4 * 4]);
        float vv[4] = {v.x, v.y, v.z, v.w};
        int base = r * FL_LDE + c4 * 4;
#pragma unroll
        for (int i = 0; i < 4; i++) {
            __half h = __float2half_rn(vv[i]);
            ea_h[base + i] = h;
            ea_l[base + i] = __float2half_rn(vv[i] - __half2float(h));
        }
    }
    __syncthreads();

    float acc[16];
#pragma unroll
    for (int e = 0; e < 16; e++) acc[e] = 0.0f;
    int we0 = warp * 16;

    for (int f0 = 0; f0 < F; f0 += 128) {
#pragma unroll
        for (int q = 0; q < 4; q++) {
            int lin = tid + q * 256;
            int r = lin >> 5, c4 = lin & 31;
            float4 v = *reinterpret_cast<const float4*>(&We[(size_t)r * F + f0 + c4 * 4]);
            float vv[4] = {v.x, v.y, v.z, v.w};
            int base = r * FL_LDW + c4 * 4;
#pragma unroll
            for (int i = 0; i < 4; i++) {
                __half h = __float2half_rn(vv[i]);
                w_h[base + i] = h;
                w_l[base + i] = __float2half_rn(vv[i] - __half2float(h));
            }
        }
        __syncthreads();

        wmma::fragment<wmma::accumulator, 16, 16, 16, float> cf[4][2];
#pragma unroll
        for (int r = 0; r < 4; r++)
#pragma unroll
            for (int c = 0; c < 2; c++) wmma::fill_fragment(cf[r][c], 0.0f);
#pragma unroll
        for (int ks = 0; ks < 2; ks++) {
            wmma::fragment<wmma::matrix_a, 16, 16, 16, __half, wmma::row_major> ah[4], al[4];
            wmma::fragment<wmma::matrix_b, 16, 16, 16, __half, wmma::row_major> bh[2], bl[2];
#pragma unroll
            for (int r = 0; r < 4; r++) {
                int aoff = (wr * 64 + r * 16) * FL_LDE + ks * 16;
                wmma::load_matrix_sync(ah[r], &ea_h[aoff], FL_LDE);
                wmma::load_matrix_sync(al[r], &ea_l[aoff], FL_LDE);
            }
#pragma unroll
            for (int c = 0; c < 2; c++) {
                int boff = (ks * 16) * FL_LDW + wc * 32 + c * 16;
                wmma::load_matrix_sync(bh[c], &w_h[boff], FL_LDW);
                wmma::load_matrix_sync(bl[c], &w_l[boff], FL_LDW);
            }
#pragma unroll
            for (int r = 0; r < 4; r++)
#pragma unroll
                for (int c = 0; c < 2; c++) {
                    wmma::mma_sync(cf[r][c], ah[r], bl[c], cf[r][c]);
                    wmma::mma_sync(cf[r][c], al[r], bh[c], cf[r][c]);
                    wmma::mma_sync(cf[r][c], ah[r], bh[c], cf[r][c]);
                }
        }
#pragma unroll
        for (int r = 0; r < 4; r++)
#pragma unroll
            for (int c = 0; c < 2; c++)
                wmma::store_matrix_sync(&sz[(wr * 64 + r * 16) * FL_LDZ + wc * 32 + c * 16],
                                        cf[r][c], FL_LDZ, wmma::mem_row_major);
        __syncthreads();

        float4 av = *reinterpret_cast<const float4*>(&att[f0 + lane * 4]);
#pragma unroll
        for (int e = 0; e < 16; e++) {
            int idx = we0 + e;
            float4 vl = *reinterpret_cast<const float4*>(xl + (size_t)s_src[idx] * F + f0 + lane * 4);
            float4 vr = *reinterpret_cast<const float4*>(xr + (size_t)s_dst[idx] * F + f0 + lane * 4);
            float4 vz = *reinterpret_cast<const float4*>(&sz[idx * FL_LDZ + lane * 4]);
            float v0 = vl.x + vr.x + vz.x; v0 = (v0 > 0.0f) ? v0 : NEG_SLOPE * v0;
            float v1 = vl.y + vr.y + vz.y; v1 = (v1 > 0.0f) ? v1 : NEG_SLOPE * v1;
            float v2 = vl.z + vr.z + vz.z; v2 = (v2 > 0.0f) ? v2 : NEG_SLOPE * v2;
            float v3 = vl.w + vr.w + vz.w; v3 = (v3 > 0.0f) ? v3 : NEG_SLOPE * v3;
            acc[e] += v0 * av.x + v1 * av.y + v2 * av.z + v3 * av.w;
        }
        __syncthreads();
    }
#pragma unroll
    for (int e = 0; e < 16; e++) {
        float a = acc[e];
#pragma unroll
        for (int o = 16; o; o >>= 1) a += __shfl_xor_sync(0xffffffffu, a, o);
        if (lane == 0) out_log[tile0 + we0 + e] = a;
    }
}

// ---------------- per-destination softmax + aggregate (+bias+relu) ----------------
template <int NR>
__global__ __launch_bounds__(256) void aggregate(const float* __restrict__ bc,
                                                 float* __restrict__ out, int F) {
    int n = blockIdx.x;
    int tid = threadIdx.x;
    int off = g_off[n];
    int deg = g_off[n + 1] - off;
    __shared__ float red[256];
    __shared__ float s_alpha[128];
    __shared__ int s_src[128];

    float eself = g_eself[n];
    float m = eself;
    for (int j = tid; j < deg; j += 256) m = fmaxf(m, g_elog[off + j]);
    red[tid] = m;
    __syncthreads();
    for (int s = 128; s > 0; s >>= 1) {
        if (tid < s) red[tid] = fmaxf(red[tid], red[tid + s]);
        __syncthreads();
    }
    m = red[0];
    __syncthreads();
    float ds = 0.0f;
    for (int j = tid; j < deg; j += 256) ds += __expf(g_elog[off + j] - m);
    red[tid] = ds;
    __syncthreads();
    for (int s = 128; s > 0; s >>= 1) {
        if (tid < s) red[tid] += red[tid + s];
        __syncthreads();
    }
    float eself_x = __expf(eself - m);
    float inv = 1.0f / (red[0] + eself_x);
    __syncthreads();

    int f0 = tid * NR;
    float acc[NR];
    const float* xln = &g_xl[(size_t)n * F];
    float aself = eself_x * inv;
#pragma unroll
    for (int i = 0; i < NR; i++) acc[i] = aself * xln[f0 + i];

    for (int c0 = 0; c0 < deg; c0 += 128) {
        int cnt = min(128, deg - c0);
        if (tid < cnt) {
            s_alpha[tid] = __expf(g_elog[off + c0 + tid] - m) * inv;
            s_src[tid] = g_ssrc[off + c0 + tid];
        }
        __syncthreads();
        for (int j = 0; j < cnt; j++) {
            const float* xs = &g_xl[(size_t)s_src[j] * F];
            float a = s_alpha[j];
            if (NR == 4) {
                float4 v = *reinterpret_cast<const float4*>(xs + f0);
                acc[0] += a * v.x; acc[1] += a * v.y;
                acc[2] += a * v.z; acc[3] += a * v.w;
            } else if (NR == 2) {
                float2 v = *reinterpret_cast<const float2*>(xs + f0);
                acc[0] += a * v.x; acc[1] += a * v.y;
            } else {
                acc[0] += a * xs[f0];
            }
        }
        __syncthreads();
    }
#pragma unroll
    for (int i = 0; i < NR; i++)
        out[(size_t)n * F + f0 + i] = fmaxf(acc[i] + bc[f0 + i], 0.0f);
}

// ---------------- pooling (batch sorted -> per-graph segment, no atomics) ----------------
__global__ __launch_bounds__(256) void pool_graph(const float* __restrict__ h,
                                                  const int* __restrict__ batch) {
    int g = blockIdx.x;
    int tid = threadIdx.x;
    __shared__ int s_lo, s_hi;
    if (tid == 0) {
        int lo = 0, hi = N_NODES;
        while (lo < hi) { int mid = (lo + hi) >> 1; if (batch[mid] < g) lo = mid + 1; else hi = mid; }
        s_lo = lo;
        lo = 0; hi = N_NODES;
        while (lo < hi) { int mid = (lo + hi) >> 1; if (batch[mid] < g + 1) lo = mid + 1; else hi = mid; }
        s_hi = lo;
    }
    __syncthreads();
    int lo = s_lo, hi = s_hi;
    float acc = 0.0f;
    for (int n = lo; n < hi; n++) acc += h[(size_t)n * 256 + tid];
    g_pool[g * 256 + tid] = acc / fmaxf((float)(hi - lo), 1.0f);
}

// ---------------- MLP head ----------------
__global__ void fc1_kernel(const float* __restrict__ fc1w, const float* __restrict__ fc1b) {
    int i = blockIdx.x * blockDim.x + threadIdx.x;
    if (i >= NGRAPH * 64) return;
    int g = i >> 6, o = i & 63;
    float s = 0.0f;
    for (int k = 0; k < 256; k++) s += g_pool[g * 256 + k] * fc1w[k * 64 + o];
    g_z[i] = s + fc1b[o];
}

__global__ __launch_bounds__(256) void head_kernel(
    const float* __restrict__ bng, const float* __restrict__ bnb,
    const float* __restrict__ fc2w, const float* __restrict__ fc2b,
    float* __restrict__ out) {
    __shared__ float z[NGRAPH * 64];
    __shared__ float mu[64], iv[64];
    int tid = threadIdx.x;
    for (int i = tid; i < NGRAPH * 64; i += 256) z[i] = g_z[i];
    __syncthreads();
    if (tid < 64) {
        float s = 0.0f, s2 = 0.0f;
        for (int g = 0; g < NGRAPH; g++) {
            float v = z[g * 64 + tid];
            s += v; s2 += v * v;
        }
        float mean = s / (float)NGRAPH;
        float var = s2 / (float)NGRAPH - mean * mean;
        mu[tid] = mean;
        iv[tid] = rsqrtf(var + 1e-5f);
    }
    __syncthreads();
    for (int i = tid; i < NGRAPH * 64; i += 256) {
        int o = i & 63;
        float v = (z[i] - mu[o]) * iv[o] * bng[o] + bnb[o];
        z[i] = fmaxf(v, 0.0f);
    }
    __syncthreads();
    if (tid < NGRAPH) {
        float s = 0.0f;
        for (int o = 0; o < 64; o++) s += z[tid * 64 + o] * fc2w[o];
        out[tid] = s + fc2b[0];
    }
}

static void launch_aggregate(const float* bc, float* hout, int F) {
    if (F == 1024)      aggregate<4><<<N_NODES, 256>>>(bc, hout, F);
    else if (F == 512)  aggregate<2><<<N_NODES, 256>>>(bc, hout, F);
    else                aggregate<1><<<N_NODES, 256>>>(bc, hout, F);
}

struct SymPtrs {
    float *hA, *hB, *xl, *xr, *loop_attr, *elog, *eself;
    __half *Ah, *Al, *B0h, *B0l, *B1h, *B1l;
    int *deg, *cur;
};

static void split_and_gemm(const float* hin, int Fin, int Fout,
                           const float* Wl, const float* bl,
                           const float* Wr, const float* br, SymPtrs& P) {
    int nA = N_NODES * Fin, nW = Fin * Fout;
    split_kernel<<<nA / 4 / 256, 256>>>(hin, P.Ah, P.Al, nA);
    split_kernel<<<(nW / 4 + 255) / 256, 256>>>(Wl, P.B0h, P.B0l, nW);
    split_kernel<<<(nW / 4 + 255) / 256, 256>>>(Wr, P.B1h, P.B1l, nW);
    dim3 g(2 * Fout / 128, N_NODES / 128);
    gemm_split<<<g, 256, GS_SMEM>>>(P.Ah, P.Al, P.B0h, P.B0l, P.B1h, P.B1l,
                                    bl, br, P.xl, P.xr, N_NODES, Fout, Fin);
}

extern "C" void kernel_launch(void* const* d_in, const int* in_sizes, int n_in,
                              void* d_out, int out_size) {
    const float* x         = (const float*)d_in[0];
    const int*   ei        = (const int*)d_in[1];
    const float* edge_attr = (const float*)d_in[2];
    const int*   batch     = (const int*)d_in[3];

    const float* Wl[3], *bl[3], *Wr[3], *br[3], *We[3], *att[3], *bc[3];
    for (int l = 0; l < 3; l++) {
        int b = 4 + l * 7;
        Wl[l]  = (const float*)d_in[b + 0];
        bl[l]  = (const float*)d_in[b + 1];
        Wr[l]  = (const float*)d_in[b + 2];
        br[l]  = (const float*)d_in[b + 3];
        We[l]  = (const float*)d_in[b + 4];
        att[l] = (const float*)d_in[b + 5];
        bc[l]  = (const float*)d_in[b + 6];
    }
    const float* fc1w = (const float*)d_in[25];
    const float* fc1b = (const float*)d_in[26];
    const float* bng  = (const float*)d_in[27];
    const float* bnb  = (const float*)d_in[28];
    const float* fc2w = (const float*)d_in[29];
    const float* fc2b = (const float*)d_in[30];
    float* out = (float*)d_out;

    const int* src = ei;
    const int* dst = ei + N_EDGES;

    static bool attr_set = false;
    if (!attr_set) {
        cudaFuncSetAttribute(fused_logit, cudaFuncAttributeMaxDynamicSharedMemorySize, FL_SMEM);
        cudaFuncSetAttribute(gemm_split, cudaFuncAttributeMaxDynamicSharedMemorySize, GS_SMEM);
        attr_set = true;
    }

    SymPtrs P;
    cudaGetSymbolAddress((void**)&P.hA, g_hA);
    cudaGetSymbolAddress((void**)&P.hB, g_hB);
    cudaGetSymbolAddress((void**)&P.xl, g_xl);
    cudaGetSymbolAddress((void**)&P.xr, g_xr);
    cudaGetSymbolAddress((void**)&P.loop_attr, g_loop_attr);
    cudaGetSymbolAddress((void**)&P.elog, g_elog);
    cudaGetSymbolAddress((void**)&P.eself, g_eself);
    cudaGetSymbolAddress((void**)&P.Ah, g_Ah);
    cudaGetSymbolAddress((void**)&P.Al, g_Al);
    cudaGetSymbolAddress((void**)&P.B0h, g_B0h);
    cudaGetSymbolAddress((void**)&P.B0l, g_B0l);
    cudaGetSymbolAddress((void**)&P.B1h, g_B1h);
    cudaGetSymbolAddress((void**)&P.B1l, g_B1l);
    cudaGetSymbolAddress((void**)&P.deg, g_deg);
    cudaGetSymbolAddress((void**)&P.cur, g_cur);

    // launches 0-2: splits; launch 3: merged layer-1 GEMM (profiled by ncu)
    split_and_gemm(x, 256, 512, Wl[0], bl[0], Wr[0], br[0], P);

    // preprocessing (independent of GEMM result)
    zero_i<<<(N_NODES + 255) / 256, 256>>>(P.deg, N_NODES);
    zero_i<<<(N_NODES + 255) / 256, 256>>>(P.cur, N_NODES);
    count_deg<<<(N_EDGES + 255) / 256, 256>>>(dst);
    scan_deg<<<1, 1024>>>();
    scatter_edges<<<(N_EDGES + 255) / 256, 256>>>(src, dst);
    loop_attr_csr<<<(N_NODES * 32 + 255) / 256, 256>>>(edge_attr);

    // layer 1 logits + aggregate
    fused_logit<<<N_EDGES / 128, 256, FL_SMEM>>>(edge_attr, We[0], att[0], P.xl, P.xr,
                                                 P.elog, 512, 0);
    fused_logit<<<N_NODES / 128, 256, FL_SMEM>>>(P.loop_attr, We[0], att[0], P.xl, P.xr,
                                                 P.eself, 512, 1);
    launch_aggregate(bc[0], P.hA, 512);

    // layer 2
    split_and_gemm(P.hA, 512, 1024, Wl[1], bl[1], Wr[1], br[1], P);
    fused_logit<<<N_EDGES / 128, 256, FL_SMEM>>>(edge_attr, We[1], att[1], P.xl, P.xr,
                                                 P.elog, 1024, 0);
    fused_logit<<<N_NODES / 128, 256, FL_SMEM>>>(P.loop_attr, We[1], att[1], P.xl, P.xr,
                                                 P.eself, 1024, 1);
    launch_aggregate(bc[1], P.hB, 1024);

    // layer 3
    split_and_gemm(P.hB, 1024, 256, Wl[2], bl[2], Wr[2], br[2], P);
    fused_logit<<<N_EDGES / 128, 256, FL_SMEM>>>(edge_attr, We[2], att[2], P.xl, P.xr,
                                                 P.elog, 256, 0);
    fused_logit<<<N_NODES / 128, 256, FL_SMEM>>>(P.loop_attr, We[2], att[2], P.xl, P.xr,
                                                 P.eself, 256, 1);
    launch_aggregate(bc[2], P.hA, 256);

    // pool + MLP head
    pool_graph<<<NGRAPH, 256>>>(P.hA, batch);
    fc1_kernel<<<(NGRAPH * 64 + 255) / 256, 256>>>(fc1w, fc1b);
    head_kernel<<<1, 256>>>(bng, bnb, fc2w, fc2b, out);
}